// round 15
// baseline (speedup 1.0000x reference)
#include <cuda_runtime.h>
#include <cuda_bf16.h>
#include <cstdint>

// Problem constants
#define N_BATCH 16
#define CD      256
#define HWSZ    1024
#define N_PIX   (N_BATCH * HWSZ)   // 16384
#define N_CODE  8192

#define OFF_ST   (N_BATCH * CD * HWSZ)
#define OFF_IDX  (2 * N_BATCH * CD * HWSZ)

#define MAXC        256
#define CAND_MARGIN 6.0e-4f
#define RESC_MARGIN 4.0e-4f
#define PAIR_CAP    (N_PIX * MAXC)

// Scratch (device globals; no allocation allowed)
__device__ float              g_zt[N_PIX * CD];
__device__ __nv_bfloat16      g_abf[N_PIX * CD];
__device__ __nv_bfloat16      g_bbf[N_CODE * CD];
__device__ float              g_zn2[N_PIX];
__device__ float              g_en2[N_CODE];
__device__ int                g_ccount[N_PIX];
__device__ float              g_cs[(size_t)N_PIX * MAXC];
__device__ int                g_ci[(size_t)N_PIX * MAXC];
__device__ unsigned long long g_best[N_PIX];    // packed (d_bits<<32)|code
__device__ unsigned int       g_npairs;
__device__ int                g_pq[PAIR_CAP];
__device__ int                g_pc[PAIR_CAP];

// ---------------- helpers ----------------
__device__ __forceinline__ uint32_t smem_u32(const void* p) {
    uint32_t a;
    asm("{ .reg .u64 t; cvta.to.shared.u64 t, %1; cvt.u32.u64 %0, t; }" : "=r"(a) : "l"(p));
    return a;
}
__device__ __forceinline__ void cp16(uint32_t dst, const void* src) {
    asm volatile("cp.async.cg.shared.global [%0], [%1], 16;"
                 :: "r"(dst), "l"(__cvta_generic_to_global(src)));
}
__device__ __forceinline__ void cp_commit() { asm volatile("cp.async.commit_group;"); }
__device__ __forceinline__ void cp_wait0()  { asm volatile("cp.async.wait_group 0;"); }

__device__ __forceinline__ float score_chain(float zz, float m, float ee) {
    return __fadd_rn(__fadd_rn(zz, -__fmul_rn(2.0f, m)), ee);
}

// ---------------- prep: transpose + bf16 A ----------------
__global__ void transpose_z_kernel(const float* __restrict__ z) {
    __shared__ float tile[32][33];
    const int n = blockIdx.z, c0 = blockIdx.y * 32, p0 = blockIdx.x * 32;
    const int tx = threadIdx.x, ty = threadIdx.y;
#pragma unroll
    for (int i = 0; i < 4; ++i) {
        int c = c0 + ty + i * 8;
        tile[ty + i * 8][tx] = z[((size_t)(n * CD + c)) * HWSZ + p0 + tx];
    }
    __syncthreads();
#pragma unroll
    for (int i = 0; i < 4; ++i) {
        int p = p0 + ty + i * 8;
        size_t idx = ((size_t)(n * HWSZ + p)) * CD + c0 + tx;
        float v = tile[tx][ty + i * 8];
        g_zt[idx]  = v;
        g_abf[idx] = __float2bfloat16(v);
    }
}

// ---------------- prep: fused norms + B convert + state init ----------------
__global__ __launch_bounds__(64)
void norms_kernel(const float* __restrict__ emb) {
    __shared__ float buf[CD];
    const int r = blockIdx.x;
    const int tid = threadIdx.x;

    if (r == 0 && tid == 0) g_npairs = 0u;

    if (r < N_PIX) {
        const float4* src = (const float4*)(g_zt + (size_t)r * CD);
        ((float4*)buf)[tid] = __ldg(&src[tid]);
        if (tid == 0) { g_ccount[r] = 0; g_best[r] = 0xFFFFFFFFFFFFFFFFull; }
        __syncthreads();
        if (tid == 0) {
            float acc = 0.f;
#pragma unroll 16
            for (int k = 0; k < CD; ++k) {
                float v = buf[k];
                acc = __fadd_rn(acc, __fmul_rn(v, v));
            }
            g_zn2[r] = acc;
        }
    } else {
        const int j = r - N_PIX;
        const float4* src = (const float4*)(emb + (size_t)j * CD);
        float4 v = __ldg(&src[tid]);
        ((float4*)buf)[tid] = v;
        __nv_bfloat162* dst = (__nv_bfloat162*)(g_bbf + (size_t)j * CD);
        dst[tid * 2]     = __floats2bfloat162_rn(v.x, v.y);
        dst[tid * 2 + 1] = __floats2bfloat162_rn(v.z, v.w);
        __syncthreads();
        if (tid == 0) {
            float acc = 0.f;
#pragma unroll 16
            for (int k = 0; k < CD; ++k) {
                float w = buf[k];
                acc = __fadd_rn(acc, __fmul_rn(w, w));
            }
            g_en2[j] = acc;
        }
    }
}

// ---------------- GEMM (mma.sync bf16) + candidate collection ----------------
// CTA: M=128 queries x N-group=1024 codes (8 blocks of 128), K=256.
#define SMA_STRIDE 264
#define SMB_STRIDE 72
#define SM_A       0
#define SM_B0      (128 * SMA_STRIDE * 2)
#define SM_BSZ     (128 * SMB_STRIDE * 2)
#define SM_B1      (SM_B0 + SM_BSZ)
#define SM_RMIN    (SM_B1 + SM_BSZ)
#define SMEM_TOTAL (SM_RMIN + 512)

__global__ __launch_bounds__(256, 2)
void gemm_cand_kernel() {
    extern __shared__ char smem[];
    const uint32_t sb = smem_u32(smem);
    const int tid = threadIdx.x, lane = tid & 31, warp = tid >> 5;
    const int warpM = warp >> 2;
    const int warpN = warp & 3;
    const int m0 = blockIdx.y * 128;
    const int g0 = blockIdx.x * 1024;
    unsigned* rowminU = (unsigned*)(smem + SM_RMIN);

    {
        const __nv_bfloat16* Ab = g_abf + (size_t)m0 * CD;
#pragma unroll
        for (int i = 0; i < 16; ++i) {
            int g = i * 256 + tid, row = g >> 5, grp = g & 31;
            cp16(sb + SM_A + row * (SMA_STRIDE * 2) + grp * 16, Ab + (size_t)row * CD + grp * 8);
        }
        cp_commit();
    }
    if (tid < 128) rowminU[tid] = 0x7F7FFFFFu;

    float zz0[4], zz1[4];
#pragma unroll
    for (int ti = 0; ti < 4; ++ti) {
        int r = m0 + warpM * 64 + ti * 16 + (lane >> 2);
        zz0[ti] = __ldg(&g_zn2[r]);
        zz1[ti] = __ldg(&g_zn2[r + 8]);
    }

    auto loadB = [&](int nbase, int kc, int buf) {
        const __nv_bfloat16* Bb = g_bbf + (size_t)nbase * CD + kc * 64;
        uint32_t dst = sb + (buf ? SM_B1 : SM_B0);
#pragma unroll
        for (int i = 0; i < 4; ++i) {
            int g = i * 256 + tid, row = g >> 3, grp = g & 7;
            cp16(dst + row * (SMB_STRIDE * 2) + grp * 16, Bb + (size_t)row * CD + grp * 8);
        }
        cp_commit();
    };

    const uint32_t aAddrBase = sb + SM_A + (warpM * 64 + (lane & 15)) * (SMA_STRIDE * 2) + (lane >> 4) * 16;
    const uint32_t bRowOff4  = (warpN * 32 + ((lane >> 4) << 3) + (lane & 7)) * (SMB_STRIDE * 2)
                             + ((lane >> 3) & 1) * 16;

    loadB(g0, 0, 0);

    for (int nb = 0; nb < 8; ++nb) {
        const int n0 = g0 + nb * 128;
        float c[4][4][4];
#pragma unroll
        for (int ti = 0; ti < 4; ++ti)
#pragma unroll
            for (int tj = 0; tj < 4; ++tj)
#pragma unroll
                for (int d = 0; d < 4; ++d) c[ti][tj][d] = 0.f;

#pragma unroll 1
        for (int kc = 0; kc < 4; ++kc) {
            const int buf = kc & 1;
            cp_wait0();
            __syncthreads();
            if (kc < 3)      loadB(n0, kc + 1, buf ^ 1);
            else if (nb < 7) loadB(n0 + 128, 0, 0);
            const uint32_t bBase = sb + (buf ? SM_B1 : SM_B0) + bRowOff4;
#pragma unroll
            for (int ks = 0; ks < 4; ++ks) {
                uint32_t a[4][4], b[2][4];
#pragma unroll
                for (int ti = 0; ti < 4; ++ti) {
                    uint32_t ad = aAddrBase + ti * 16 * (SMA_STRIDE * 2) + (kc * 64 + ks * 16) * 2;
                    asm volatile("ldmatrix.sync.aligned.m8n8.x4.shared.b16 {%0,%1,%2,%3}, [%4];"
                                 : "=r"(a[ti][0]), "=r"(a[ti][1]), "=r"(a[ti][2]), "=r"(a[ti][3])
                                 : "r"(ad));
                }
#pragma unroll
                for (int tjp = 0; tjp < 2; ++tjp) {
                    uint32_t bd = bBase + tjp * 16 * (SMB_STRIDE * 2) + (ks * 16) * 2;
                    asm volatile("ldmatrix.sync.aligned.m8n8.x4.shared.b16 {%0,%1,%2,%3}, [%4];"
                                 : "=r"(b[tjp][0]), "=r"(b[tjp][1]), "=r"(b[tjp][2]), "=r"(b[tjp][3])
                                 : "r"(bd));
                }
#pragma unroll
                for (int ti = 0; ti < 4; ++ti)
#pragma unroll
                    for (int tj = 0; tj < 4; ++tj) {
                        const uint32_t* bb = &b[tj >> 1][(tj & 1) * 2];
                        asm volatile(
                            "mma.sync.aligned.m16n8k16.row.col.f32.bf16.bf16.f32 "
                            "{%0,%1,%2,%3}, {%4,%5,%6,%7}, {%8,%9}, {%0,%1,%2,%3};"
                            : "+f"(c[ti][tj][0]), "+f"(c[ti][tj][1]),
                              "+f"(c[ti][tj][2]), "+f"(c[ti][tj][3])
                            : "r"(a[ti][0]), "r"(a[ti][1]), "r"(a[ti][2]), "r"(a[ti][3]),
                              "r"(bb[0]), "r"(bb[1]));
                    }
            }
        }

        float ee0[4], ee1[4];
#pragma unroll
        for (int tj = 0; tj < 4; ++tj) {
            int cidx = n0 + warpN * 32 + tj * 8 + 2 * (lane & 3);
            ee0[tj] = __ldg(&g_en2[cidx]);
            ee1[tj] = __ldg(&g_en2[cidx + 1]);
        }
#pragma unroll
        for (int ti = 0; ti < 4; ++ti) {
            float mn0 = 3.4e38f, mn1 = 3.4e38f;
#pragma unroll
            for (int tj = 0; tj < 4; ++tj) {
                float s0 = score_chain(zz0[ti], c[ti][tj][0], ee0[tj]);
                float s1 = score_chain(zz0[ti], c[ti][tj][1], ee1[tj]);
                float s2 = score_chain(zz1[ti], c[ti][tj][2], ee0[tj]);
                float s3 = score_chain(zz1[ti], c[ti][tj][3], ee1[tj]);
                c[ti][tj][0] = s0; c[ti][tj][1] = s1; c[ti][tj][2] = s2; c[ti][tj][3] = s3;
                mn0 = fminf(mn0, fminf(s0, s1));
                mn1 = fminf(mn1, fminf(s2, s3));
            }
            int r0 = warpM * 64 + ti * 16 + (lane >> 2);
            atomicMin(&rowminU[r0],     __float_as_uint(mn0));
            atomicMin(&rowminU[r0 + 8], __float_as_uint(mn1));
        }
        __syncthreads();
#pragma unroll
        for (int ti = 0; ti < 4; ++ti) {
            int r0 = warpM * 64 + ti * 16 + (lane >> 2);
            float t0 = __uint_as_float(rowminU[r0])     + CAND_MARGIN;
            float t1 = __uint_as_float(rowminU[r0 + 8]) + CAND_MARGIN;
            int q0 = m0 + r0, q1 = q0 + 8;
#pragma unroll
            for (int tj = 0; tj < 4; ++tj) {
                int cb = n0 + warpN * 32 + tj * 8 + 2 * (lane & 3);
                if (c[ti][tj][0] <= t0) {
                    int pos = atomicAdd(&g_ccount[q0], 1);
                    if (pos < MAXC) { g_cs[(size_t)q0 * MAXC + pos] = c[ti][tj][0]; g_ci[(size_t)q0 * MAXC + pos] = cb; }
                }
                if (c[ti][tj][1] <= t0) {
                    int pos = atomicAdd(&g_ccount[q0], 1);
                    if (pos < MAXC) { g_cs[(size_t)q0 * MAXC + pos] = c[ti][tj][1]; g_ci[(size_t)q0 * MAXC + pos] = cb + 1; }
                }
                if (c[ti][tj][2] <= t1) {
                    int pos = atomicAdd(&g_ccount[q1], 1);
                    if (pos < MAXC) { g_cs[(size_t)q1 * MAXC + pos] = c[ti][tj][2]; g_ci[(size_t)q1 * MAXC + pos] = cb; }
                }
                if (c[ti][tj][3] <= t1) {
                    int pos = atomicAdd(&g_ccount[q1], 1);
                    if (pos < MAXC) { g_cs[(size_t)q1 * MAXC + pos] = c[ti][tj][3]; g_ci[(size_t)q1 * MAXC + pos] = cb + 1; }
                }
            }
        }
        __syncthreads();
    }
}

// ---------------- rescue phase A: survivor compaction, block-aggregated -----
__global__ __launch_bounds__(256)
void rescueA_kernel() {
    __shared__ int      blkCount;
    __shared__ unsigned gbase;
    __shared__ int      bq[512], bc[512];
    const int tid = threadIdx.x, lane = tid & 31, w = tid >> 5;
    const int q = blockIdx.x * 8 + w;
    if (tid == 0) blkCount = 0;
    __syncthreads();

    const int cnt = g_ccount[q];
    if (cnt <= 32) {
        float s = 3.4e38f; int ci = 0;
        if (lane < cnt) {
            s  = g_cs[(size_t)q * MAXC + lane];
            ci = g_ci[(size_t)q * MAXC + lane];
        }
        float mn = s;
#pragma unroll
        for (int o = 16; o; o >>= 1) mn = fminf(mn, __shfl_xor_sync(0xFFFFFFFFu, mn, o));
        bool pred = (lane < cnt) && (s <= mn + RESC_MARGIN);
        unsigned mask = __ballot_sync(0xFFFFFFFFu, pred);
        if (mask) {
            int leader = __ffs(mask) - 1;
            int base = 0;
            if (lane == leader) base = atomicAdd(&blkCount, __popc(mask));
            base = __shfl_sync(0xFFFFFFFFu, base, leader);
            if (pred) {
                int off = base + __popc(mask & ((1u << lane) - 1u));
                bq[off] = q; bc[off] = ci;
            }
        }
    } else if (cnt <= MAXC) {
        unsigned long long abest = 0xFFFFFFFFFFFFFFFFull;
        for (int base = 0; base < cnt; base += 32) {
            int i = base + lane;
            if (i < cnt) {
                float s = g_cs[(size_t)q * MAXC + i];
                unsigned long long k =
                    ((unsigned long long)__float_as_uint(s) << 32) | (unsigned)g_ci[(size_t)q * MAXC + i];
                abest = min(abest, k);
            }
        }
#pragma unroll
        for (int o = 16; o; o >>= 1) abest = min(abest, __shfl_xor_sync(0xFFFFFFFFu, abest, o));
        const float thr = __uint_as_float((uint32_t)(abest >> 32)) + RESC_MARGIN;
        for (int base = 0; base < cnt; base += 32) {
            int i = base + lane;
            bool pred = (i < cnt) && (g_cs[(size_t)q * MAXC + i] <= thr);
            unsigned mask = __ballot_sync(0xFFFFFFFFu, pred);
            if (!mask) continue;
            int leader = __ffs(mask) - 1;
            unsigned pbase = 0;
            if (lane == leader) pbase = atomicAdd(&g_npairs, (unsigned)__popc(mask));
            pbase = __shfl_sync(0xFFFFFFFFu, pbase, leader);
            if (pred) {
                unsigned off = pbase + __popc(mask & ((1u << lane) - 1u));
                if (off < PAIR_CAP) {
                    g_pq[off] = q;
                    g_pc[off] = g_ci[(size_t)q * MAXC + i];
                }
            }
        }
    } else {
        unsigned base;
        if (lane == 0) base = atomicAdd(&g_npairs, (unsigned)N_CODE);
        base = __shfl_sync(0xFFFFFFFFu, base, 0);
        if (base + N_CODE <= PAIR_CAP) {
            for (int j = lane; j < N_CODE; j += 32) {
                g_pq[base + j] = q; g_pc[base + j] = j;
            }
        }
    }

    __syncthreads();
    if (tid == 0 && blkCount > 0) gbase = atomicAdd(&g_npairs, (unsigned)blkCount);
    __syncthreads();
    for (int i = tid; i < blkCount; i += 256) {
        unsigned off = gbase + i;
        if (off < PAIR_CAP) { g_pq[off] = bq[i]; g_pc[off] = bc[i]; }
    }
}

// ---------------- rescue phase B: dense exact eval (thread per pair) --------
__global__ __launch_bounds__(256)
void rescueB_kernel(const float* __restrict__ emb) {
    unsigned n = g_npairs;
    if (n > PAIR_CAP) n = PAIR_CAP;
    const unsigned stride = gridDim.x * blockDim.x;
    for (unsigned i = blockIdx.x * blockDim.x + threadIdx.x; i < n; i += stride) {
        const int q = g_pq[i];
        const int code = g_pc[i];
        const float4* zr = (const float4*)(g_zt + (size_t)q * CD);
        const float4* er = (const float4*)(emb + (size_t)code * CD);
        float acc = 0.f;
#pragma unroll 8
        for (int k4 = 0; k4 < CD / 4; ++k4) {
            float4 a = __ldg(&zr[k4]);
            float4 b = __ldg(&er[k4]);
            acc = fmaf(a.x, b.x, acc);
            acc = fmaf(a.y, b.y, acc);
            acc = fmaf(a.z, b.z, acc);
            acc = fmaf(a.w, b.w, acc);
        }
        float d = __fadd_rn(__fadd_rn(__ldg(&g_zn2[q]), -__fmul_rn(2.0f, acc)), __ldg(&g_en2[code]));
        unsigned long long key = ((unsigned long long)__float_as_uint(d) << 32) | (unsigned)code;
        atomicMin(&g_best[q], key);
    }
}

// ---------------- gather: smem-transposed (coalesced emb reads) -------------
__global__ __launch_bounds__(256)
void gather_kernel(const float* __restrict__ z, const float* __restrict__ emb,
                   float* __restrict__ out) {
    __shared__ float sq[32][257];
    __shared__ int   sidx[32];
    const int tid = threadIdx.x, lane = tid & 31, w = tid >> 5;
    const int p0 = blockIdx.x * 32;

    if (tid < 32) sidx[tid] = (int)(g_best[p0 + tid] & 0x1FFFull);
    __syncthreads();

#pragma unroll
    for (int k = 0; k < 4; ++k) {
        int pp = w * 4 + k;
        const float4* er = (const float4*)(emb + (size_t)sidx[pp] * CD);
        float4 a = __ldg(&er[lane]);
        float4 b = __ldg(&er[lane + 32]);
        sq[pp][lane * 4 + 0]   = a.x; sq[pp][lane * 4 + 1]   = a.y;
        sq[pp][lane * 4 + 2]   = a.z; sq[pp][lane * 4 + 3]   = a.w;
        sq[pp][128 + lane * 4 + 0] = b.x; sq[pp][128 + lane * 4 + 1] = b.y;
        sq[pp][128 + lane * 4 + 2] = b.z; sq[pp][128 + lane * 4 + 3] = b.w;
    }
    __syncthreads();

    const int p  = p0 + lane;
    const int n  = p >> 10;
    const int hw = p & 1023;
    const size_t base = (size_t)n * (CD * HWSZ) + hw;
#pragma unroll
    for (int cc = 0; cc < CD / 8; ++cc) {
        int c = cc * 8 + w;
        float qv = sq[lane][c];
        size_t off = base + (size_t)c * HWSZ;
        out[off] = qv;
        float zv = z[off];
        out[OFF_ST + off] = __fadd_rn(zv, __fadd_rn(qv, -zv));
    }
    if (w == 0) out[OFF_IDX + p] = (float)sidx[lane];
}

// ---------------------------------------------------------------------------
extern "C" void kernel_launch(void* const* d_in, const int* in_sizes, int n_in,
                              void* d_out, int out_size) {
    const float* z   = (const float*)d_in[0];
    const float* emb = (const float*)d_in[1];
    float* out = (float*)d_out;

    cudaFuncSetAttribute(gemm_cand_kernel, cudaFuncAttributeMaxDynamicSharedMemorySize, SMEM_TOTAL);

    transpose_z_kernel<<<dim3(32, 8, 16), dim3(32, 8)>>>(z);
    norms_kernel<<<N_PIX + N_CODE, 64>>>(emb);
    gemm_cand_kernel<<<dim3(N_CODE / 1024, N_PIX / 128), 256, SMEM_TOTAL>>>();
    rescueA_kernel<<<N_PIX / 8, 256>>>();
    rescueB_kernel<<<512, 256>>>(emb);
    gather_kernel<<<N_PIX / 32, 256>>>(z, emb, out);
}

// round 16
// speedup vs baseline: 1.4603x; 1.4603x over previous
#include <cuda_runtime.h>
#include <cuda_bf16.h>
#include <cstdint>

// Problem constants
#define N_BATCH 16
#define CD      256
#define HWSZ    1024
#define N_PIX   (N_BATCH * HWSZ)   // 16384
#define N_CODE  8192

#define OFF_ST   (N_BATCH * CD * HWSZ)
#define OFF_IDX  (2 * N_BATCH * CD * HWSZ)

#define MAXC        256
#define CAND_MARGIN 6.0e-4f
#define RESC_MARGIN 4.0e-4f
#define PAIR_CAP    (N_PIX * MAXC)

// Scratch (device globals; no allocation allowed)
__device__ float              g_zt[N_PIX * CD];
__device__ __nv_bfloat16      g_abf[N_PIX * CD];
__device__ __nv_bfloat16      g_bbf[N_CODE * CD];
__device__ float              g_zn2[N_PIX];
__device__ float              g_en2[N_CODE];
__device__ int                g_ccount[N_PIX];
__device__ float              g_cs[(size_t)N_PIX * MAXC];
__device__ int                g_ci[(size_t)N_PIX * MAXC];
__device__ unsigned long long g_best[N_PIX];    // packed (d_bits<<32)|code
__device__ unsigned int       g_npairs;
__device__ int                g_pq[PAIR_CAP];
__device__ int                g_pc[PAIR_CAP];

// ---------------- helpers ----------------
__device__ __forceinline__ uint32_t smem_u32(const void* p) {
    uint32_t a;
    asm("{ .reg .u64 t; cvta.to.shared.u64 t, %1; cvt.u32.u64 %0, t; }" : "=r"(a) : "l"(p));
    return a;
}
__device__ __forceinline__ void cp16(uint32_t dst, const void* src) {
    asm volatile("cp.async.cg.shared.global [%0], [%1], 16;"
                 :: "r"(dst), "l"(__cvta_generic_to_global(src)));
}
__device__ __forceinline__ void cp_commit() { asm volatile("cp.async.commit_group;"); }
__device__ __forceinline__ void cp_wait0()  { asm volatile("cp.async.wait_group 0;"); }

__device__ __forceinline__ float score_chain(float zz, float m, float ee) {
    return __fadd_rn(__fadd_rn(zz, -__fmul_rn(2.0f, m)), ee);
}

// ---------------- prep: transpose + bf16 A ----------------
__global__ void transpose_z_kernel(const float* __restrict__ z) {
    __shared__ float tile[32][33];
    const int n = blockIdx.z, c0 = blockIdx.y * 32, p0 = blockIdx.x * 32;
    const int tx = threadIdx.x, ty = threadIdx.y;
#pragma unroll
    for (int i = 0; i < 4; ++i) {
        int c = c0 + ty + i * 8;
        tile[ty + i * 8][tx] = z[((size_t)(n * CD + c)) * HWSZ + p0 + tx];
    }
    __syncthreads();
#pragma unroll
    for (int i = 0; i < 4; ++i) {
        int p = p0 + ty + i * 8;
        size_t idx = ((size_t)(n * HWSZ + p)) * CD + c0 + tx;
        float v = tile[tx][ty + i * 8];
        g_zt[idx]  = v;
        g_abf[idx] = __float2bfloat16(v);
    }
}

// ---------------- prep: fused norms + B convert + state init ----------------
__global__ __launch_bounds__(64)
void norms_kernel(const float* __restrict__ emb) {
    __shared__ float buf[CD];
    const int r = blockIdx.x;
    const int tid = threadIdx.x;

    if (r == 0 && tid == 0) g_npairs = 0u;

    if (r < N_PIX) {
        const float4* src = (const float4*)(g_zt + (size_t)r * CD);
        ((float4*)buf)[tid] = __ldg(&src[tid]);
        if (tid == 0) { g_ccount[r] = 0; g_best[r] = 0xFFFFFFFFFFFFFFFFull; }
        __syncthreads();
        if (tid == 0) {
            float acc = 0.f;
#pragma unroll 16
            for (int k = 0; k < CD; ++k) {
                float v = buf[k];
                acc = __fadd_rn(acc, __fmul_rn(v, v));
            }
            g_zn2[r] = acc;
        }
    } else {
        const int j = r - N_PIX;
        const float4* src = (const float4*)(emb + (size_t)j * CD);
        float4 v = __ldg(&src[tid]);
        ((float4*)buf)[tid] = v;
        __nv_bfloat162* dst = (__nv_bfloat162*)(g_bbf + (size_t)j * CD);
        dst[tid * 2]     = __floats2bfloat162_rn(v.x, v.y);
        dst[tid * 2 + 1] = __floats2bfloat162_rn(v.z, v.w);
        __syncthreads();
        if (tid == 0) {
            float acc = 0.f;
#pragma unroll 16
            for (int k = 0; k < CD; ++k) {
                float w = buf[k];
                acc = __fadd_rn(acc, __fmul_rn(w, w));
            }
            g_en2[j] = acc;
        }
    }
}

// ---------------- GEMM (mma.sync bf16) + candidate collection ----------------
// CTA: M=128 queries x N-group=1024 codes (8 blocks of 128), K=256.
#define SMA_STRIDE 264
#define SMB_STRIDE 72
#define SM_A       0
#define SM_B0      (128 * SMA_STRIDE * 2)
#define SM_BSZ     (128 * SMB_STRIDE * 2)
#define SM_B1      (SM_B0 + SM_BSZ)
#define SM_RMIN    (SM_B1 + SM_BSZ)
#define SMEM_TOTAL (SM_RMIN + 512)

__global__ __launch_bounds__(256, 2)
void gemm_cand_kernel() {
    extern __shared__ char smem[];
    const uint32_t sb = smem_u32(smem);
    const int tid = threadIdx.x, lane = tid & 31, warp = tid >> 5;
    const int warpM = warp >> 2;
    const int warpN = warp & 3;
    const int m0 = blockIdx.y * 128;
    const int g0 = blockIdx.x * 1024;
    unsigned* rowminU = (unsigned*)(smem + SM_RMIN);

    {
        const __nv_bfloat16* Ab = g_abf + (size_t)m0 * CD;
#pragma unroll
        for (int i = 0; i < 16; ++i) {
            int g = i * 256 + tid, row = g >> 5, grp = g & 31;
            cp16(sb + SM_A + row * (SMA_STRIDE * 2) + grp * 16, Ab + (size_t)row * CD + grp * 8);
        }
        cp_commit();
    }
    if (tid < 128) rowminU[tid] = 0x7F7FFFFFu;

    float zz0[4], zz1[4];
#pragma unroll
    for (int ti = 0; ti < 4; ++ti) {
        int r = m0 + warpM * 64 + ti * 16 + (lane >> 2);
        zz0[ti] = __ldg(&g_zn2[r]);
        zz1[ti] = __ldg(&g_zn2[r + 8]);
    }

    auto loadB = [&](int nbase, int kc, int buf) {
        const __nv_bfloat16* Bb = g_bbf + (size_t)nbase * CD + kc * 64;
        uint32_t dst = sb + (buf ? SM_B1 : SM_B0);
#pragma unroll
        for (int i = 0; i < 4; ++i) {
            int g = i * 256 + tid, row = g >> 3, grp = g & 7;
            cp16(dst + row * (SMB_STRIDE * 2) + grp * 16, Bb + (size_t)row * CD + grp * 8);
        }
        cp_commit();
    };

    const uint32_t aAddrBase = sb + SM_A + (warpM * 64 + (lane & 15)) * (SMA_STRIDE * 2) + (lane >> 4) * 16;
    const uint32_t bRowOff4  = (warpN * 32 + ((lane >> 4) << 3) + (lane & 7)) * (SMB_STRIDE * 2)
                             + ((lane >> 3) & 1) * 16;

    loadB(g0, 0, 0);

    for (int nb = 0; nb < 8; ++nb) {
        const int n0 = g0 + nb * 128;
        float c[4][4][4];
#pragma unroll
        for (int ti = 0; ti < 4; ++ti)
#pragma unroll
            for (int tj = 0; tj < 4; ++tj)
#pragma unroll
                for (int d = 0; d < 4; ++d) c[ti][tj][d] = 0.f;

#pragma unroll 1
        for (int kc = 0; kc < 4; ++kc) {
            const int buf = kc & 1;
            cp_wait0();
            __syncthreads();
            if (kc < 3)      loadB(n0, kc + 1, buf ^ 1);
            else if (nb < 7) loadB(n0 + 128, 0, 0);
            const uint32_t bBase = sb + (buf ? SM_B1 : SM_B0) + bRowOff4;
#pragma unroll
            for (int ks = 0; ks < 4; ++ks) {
                uint32_t a[4][4], b[2][4];
#pragma unroll
                for (int ti = 0; ti < 4; ++ti) {
                    uint32_t ad = aAddrBase + ti * 16 * (SMA_STRIDE * 2) + (kc * 64 + ks * 16) * 2;
                    asm volatile("ldmatrix.sync.aligned.m8n8.x4.shared.b16 {%0,%1,%2,%3}, [%4];"
                                 : "=r"(a[ti][0]), "=r"(a[ti][1]), "=r"(a[ti][2]), "=r"(a[ti][3])
                                 : "r"(ad));
                }
#pragma unroll
                for (int tjp = 0; tjp < 2; ++tjp) {
                    uint32_t bd = bBase + tjp * 16 * (SMB_STRIDE * 2) + (ks * 16) * 2;
                    asm volatile("ldmatrix.sync.aligned.m8n8.x4.shared.b16 {%0,%1,%2,%3}, [%4];"
                                 : "=r"(b[tjp][0]), "=r"(b[tjp][1]), "=r"(b[tjp][2]), "=r"(b[tjp][3])
                                 : "r"(bd));
                }
#pragma unroll
                for (int ti = 0; ti < 4; ++ti)
#pragma unroll
                    for (int tj = 0; tj < 4; ++tj) {
                        const uint32_t* bb = &b[tj >> 1][(tj & 1) * 2];
                        asm volatile(
                            "mma.sync.aligned.m16n8k16.row.col.f32.bf16.bf16.f32 "
                            "{%0,%1,%2,%3}, {%4,%5,%6,%7}, {%8,%9}, {%0,%1,%2,%3};"
                            : "+f"(c[ti][tj][0]), "+f"(c[ti][tj][1]),
                              "+f"(c[ti][tj][2]), "+f"(c[ti][tj][3])
                            : "r"(a[ti][0]), "r"(a[ti][1]), "r"(a[ti][2]), "r"(a[ti][3]),
                              "r"(bb[0]), "r"(bb[1]));
                    }
            }
        }

        float ee0[4], ee1[4];
#pragma unroll
        for (int tj = 0; tj < 4; ++tj) {
            int cidx = n0 + warpN * 32 + tj * 8 + 2 * (lane & 3);
            ee0[tj] = __ldg(&g_en2[cidx]);
            ee1[tj] = __ldg(&g_en2[cidx + 1]);
        }
#pragma unroll
        for (int ti = 0; ti < 4; ++ti) {
            float mn0 = 3.4e38f, mn1 = 3.4e38f;
#pragma unroll
            for (int tj = 0; tj < 4; ++tj) {
                float s0 = score_chain(zz0[ti], c[ti][tj][0], ee0[tj]);
                float s1 = score_chain(zz0[ti], c[ti][tj][1], ee1[tj]);
                float s2 = score_chain(zz1[ti], c[ti][tj][2], ee0[tj]);
                float s3 = score_chain(zz1[ti], c[ti][tj][3], ee1[tj]);
                c[ti][tj][0] = s0; c[ti][tj][1] = s1; c[ti][tj][2] = s2; c[ti][tj][3] = s3;
                mn0 = fminf(mn0, fminf(s0, s1));
                mn1 = fminf(mn1, fminf(s2, s3));
            }
            int r0 = warpM * 64 + ti * 16 + (lane >> 2);
            atomicMin(&rowminU[r0],     __float_as_uint(mn0));
            atomicMin(&rowminU[r0 + 8], __float_as_uint(mn1));
        }
        __syncthreads();
#pragma unroll
        for (int ti = 0; ti < 4; ++ti) {
            int r0 = warpM * 64 + ti * 16 + (lane >> 2);
            float t0 = __uint_as_float(rowminU[r0])     + CAND_MARGIN;
            float t1 = __uint_as_float(rowminU[r0 + 8]) + CAND_MARGIN;
            int q0 = m0 + r0, q1 = q0 + 8;
#pragma unroll
            for (int tj = 0; tj < 4; ++tj) {
                int cb = n0 + warpN * 32 + tj * 8 + 2 * (lane & 3);
                if (c[ti][tj][0] <= t0) {
                    int pos = atomicAdd(&g_ccount[q0], 1);
                    if (pos < MAXC) { g_cs[(size_t)q0 * MAXC + pos] = c[ti][tj][0]; g_ci[(size_t)q0 * MAXC + pos] = cb; }
                }
                if (c[ti][tj][1] <= t0) {
                    int pos = atomicAdd(&g_ccount[q0], 1);
                    if (pos < MAXC) { g_cs[(size_t)q0 * MAXC + pos] = c[ti][tj][1]; g_ci[(size_t)q0 * MAXC + pos] = cb + 1; }
                }
                if (c[ti][tj][2] <= t1) {
                    int pos = atomicAdd(&g_ccount[q1], 1);
                    if (pos < MAXC) { g_cs[(size_t)q1 * MAXC + pos] = c[ti][tj][2]; g_ci[(size_t)q1 * MAXC + pos] = cb; }
                }
                if (c[ti][tj][3] <= t1) {
                    int pos = atomicAdd(&g_ccount[q1], 1);
                    if (pos < MAXC) { g_cs[(size_t)q1 * MAXC + pos] = c[ti][tj][3]; g_ci[(size_t)q1 * MAXC + pos] = cb + 1; }
                }
            }
        }
        __syncthreads();
    }
}

// ---------------- rescue phase A: survivor compaction, block-aggregated -----
__global__ __launch_bounds__(256)
void rescueA_kernel() {
    __shared__ int      blkCount;
    __shared__ unsigned gbase;
    __shared__ int      bq[512], bc[512];
    const int tid = threadIdx.x, lane = tid & 31, w = tid >> 5;
    const int q = blockIdx.x * 8 + w;
    if (tid == 0) blkCount = 0;
    __syncthreads();

    const int cnt = g_ccount[q];
    if (cnt <= 32) {
        float s = 3.4e38f; int ci = 0;
        if (lane < cnt) {
            s  = g_cs[(size_t)q * MAXC + lane];
            ci = g_ci[(size_t)q * MAXC + lane];
        }
        float mn = s;
#pragma unroll
        for (int o = 16; o; o >>= 1) mn = fminf(mn, __shfl_xor_sync(0xFFFFFFFFu, mn, o));
        bool pred = (lane < cnt) && (s <= mn + RESC_MARGIN);
        unsigned mask = __ballot_sync(0xFFFFFFFFu, pred);
        if (mask) {
            int leader = __ffs(mask) - 1;
            int base = 0;
            if (lane == leader) base = atomicAdd(&blkCount, __popc(mask));
            base = __shfl_sync(0xFFFFFFFFu, base, leader);
            if (pred) {
                int off = base + __popc(mask & ((1u << lane) - 1u));
                bq[off] = q; bc[off] = ci;
            }
        }
    } else if (cnt <= MAXC) {
        unsigned long long abest = 0xFFFFFFFFFFFFFFFFull;
        for (int base = 0; base < cnt; base += 32) {
            int i = base + lane;
            if (i < cnt) {
                float s = g_cs[(size_t)q * MAXC + i];
                unsigned long long k =
                    ((unsigned long long)__float_as_uint(s) << 32) | (unsigned)g_ci[(size_t)q * MAXC + i];
                abest = min(abest, k);
            }
        }
#pragma unroll
        for (int o = 16; o; o >>= 1) abest = min(abest, __shfl_xor_sync(0xFFFFFFFFu, abest, o));
        const float thr = __uint_as_float((uint32_t)(abest >> 32)) + RESC_MARGIN;
        for (int base = 0; base < cnt; base += 32) {
            int i = base + lane;
            bool pred = (i < cnt) && (g_cs[(size_t)q * MAXC + i] <= thr);
            unsigned mask = __ballot_sync(0xFFFFFFFFu, pred);
            if (!mask) continue;
            int leader = __ffs(mask) - 1;
            unsigned pbase = 0;
            if (lane == leader) pbase = atomicAdd(&g_npairs, (unsigned)__popc(mask));
            pbase = __shfl_sync(0xFFFFFFFFu, pbase, leader);
            if (pred) {
                unsigned off = pbase + __popc(mask & ((1u << lane) - 1u));
                if (off < PAIR_CAP) {
                    g_pq[off] = q;
                    g_pc[off] = g_ci[(size_t)q * MAXC + i];
                }
            }
        }
    } else {
        unsigned base;
        if (lane == 0) base = atomicAdd(&g_npairs, (unsigned)N_CODE);
        base = __shfl_sync(0xFFFFFFFFu, base, 0);
        if (base + N_CODE <= PAIR_CAP) {
            for (int j = lane; j < N_CODE; j += 32) {
                g_pq[base + j] = q; g_pc[base + j] = j;
            }
        }
    }

    __syncthreads();
    if (tid == 0 && blkCount > 0) gbase = atomicAdd(&g_npairs, (unsigned)blkCount);
    __syncthreads();
    for (int i = tid; i < blkCount; i += 256) {
        unsigned off = gbase + i;
        if (off < PAIR_CAP) { g_pq[off] = bq[i]; g_pc[off] = bc[i]; }
    }
}

// ---------------- rescue phase B: dense exact eval (thread per pair) --------
__global__ __launch_bounds__(256)
void rescueB_kernel(const float* __restrict__ emb) {
    unsigned n = g_npairs;
    if (n > PAIR_CAP) n = PAIR_CAP;
    const unsigned stride = gridDim.x * blockDim.x;
    for (unsigned i = blockIdx.x * blockDim.x + threadIdx.x; i < n; i += stride) {
        const int q = g_pq[i];
        const int code = g_pc[i];
        const float4* zr = (const float4*)(g_zt + (size_t)q * CD);
        const float4* er = (const float4*)(emb + (size_t)code * CD);
        float acc = 0.f;
#pragma unroll 8
        for (int k4 = 0; k4 < CD / 4; ++k4) {
            float4 a = __ldg(&zr[k4]);
            float4 b = __ldg(&er[k4]);
            acc = fmaf(a.x, b.x, acc);
            acc = fmaf(a.y, b.y, acc);
            acc = fmaf(a.z, b.z, acc);
            acc = fmaf(a.w, b.w, acc);
        }
        float d = __fadd_rn(__fadd_rn(__ldg(&g_zn2[q]), -__fmul_rn(2.0f, acc)), __ldg(&g_en2[code]));
        unsigned long long key = ((unsigned long long)__float_as_uint(d) << 32) | (unsigned)code;
        atomicMin(&g_best[q], key);
    }
}

// ---------------- gather: smem-transposed (coalesced emb reads) -------------
__global__ __launch_bounds__(256)
void gather_kernel(const float* __restrict__ z, const float* __restrict__ emb,
                   float* __restrict__ out) {
    __shared__ float sq[32][257];
    __shared__ int   sidx[32];
    const int tid = threadIdx.x, lane = tid & 31, w = tid >> 5;
    const int p0 = blockIdx.x * 32;

    if (tid < 32) sidx[tid] = (int)(g_best[p0 + tid] & 0x1FFFull);
    __syncthreads();

#pragma unroll
    for (int k = 0; k < 4; ++k) {
        int pp = w * 4 + k;
        const float4* er = (const float4*)(emb + (size_t)sidx[pp] * CD);
        float4 a = __ldg(&er[lane]);
        float4 b = __ldg(&er[lane + 32]);
        sq[pp][lane * 4 + 0]   = a.x; sq[pp][lane * 4 + 1]   = a.y;
        sq[pp][lane * 4 + 2]   = a.z; sq[pp][lane * 4 + 3]   = a.w;
        sq[pp][128 + lane * 4 + 0] = b.x; sq[pp][128 + lane * 4 + 1] = b.y;
        sq[pp][128 + lane * 4 + 2] = b.z; sq[pp][128 + lane * 4 + 3] = b.w;
    }
    __syncthreads();

    const int p  = p0 + lane;
    const int n  = p >> 10;
    const int hw = p & 1023;
    const size_t base = (size_t)n * (CD * HWSZ) + hw;
#pragma unroll
    for (int cc = 0; cc < CD / 8; ++cc) {
        int c = cc * 8 + w;
        float qv = sq[lane][c];
        size_t off = base + (size_t)c * HWSZ;
        out[off] = qv;
        float zv = z[off];
        out[OFF_ST + off] = __fadd_rn(zv, __fadd_rn(qv, -zv));
    }
    if (w == 0) out[OFF_IDX + p] = (float)sidx[lane];
}

// ---------------------------------------------------------------------------
extern "C" void kernel_launch(void* const* d_in, const int* in_sizes, int n_in,
                              void* d_out, int out_size) {
    const float* z   = (const float*)d_in[0];
    const float* emb = (const float*)d_in[1];
    float* out = (float*)d_out;

    cudaFuncSetAttribute(gemm_cand_kernel, cudaFuncAttributeMaxDynamicSharedMemorySize, SMEM_TOTAL);

    transpose_z_kernel<<<dim3(32, 8, 16), dim3(32, 8)>>>(z);
    norms_kernel<<<N_PIX + N_CODE, 64>>>(emb);
    gemm_cand_kernel<<<dim3(N_CODE / 1024, N_PIX / 128), 256, SMEM_TOTAL>>>();
    rescueA_kernel<<<N_PIX / 8, 256>>>();
    rescueB_kernel<<<512, 256>>>(emb);
    gather_kernel<<<N_PIX / 32, 256>>>(z, emb, out);
}

// round 17
// speedup vs baseline: 1.5202x; 1.0410x over previous
#include <cuda_runtime.h>
#include <cuda_bf16.h>
#include <cstdint>

// Problem constants
#define N_BATCH 16
#define CD      256
#define HWSZ    1024
#define N_PIX   (N_BATCH * HWSZ)   // 16384
#define N_CODE  8192

#define OFF_ST   (N_BATCH * CD * HWSZ)
#define OFF_IDX  (2 * N_BATCH * CD * HWSZ)

#define MAXC        256
#define CAND_MARGIN 6.0e-4f
#define RESC_MARGIN 4.0e-4f
#define PAIR_CAP    (N_PIX * MAXC)

// Scratch (device globals; no allocation allowed)
__device__ float              g_zt[N_PIX * CD];
__device__ __nv_bfloat16      g_abf[N_PIX * CD];
__device__ __nv_bfloat16      g_bbf[N_CODE * CD];
__device__ float              g_zn2[N_PIX];
__device__ float              g_en2[N_CODE];
__device__ int                g_ccount[N_PIX];
__device__ float              g_cs[(size_t)N_PIX * MAXC];
__device__ int                g_ci[(size_t)N_PIX * MAXC];
__device__ unsigned long long g_best[N_PIX];    // packed (d_bits<<32)|code
__device__ unsigned int       g_npairs;
__device__ int                g_pq[PAIR_CAP];
__device__ int                g_pc[PAIR_CAP];

// ---------------- helpers ----------------
__device__ __forceinline__ uint32_t smem_u32(const void* p) {
    uint32_t a;
    asm("{ .reg .u64 t; cvta.to.shared.u64 t, %1; cvt.u32.u64 %0, t; }" : "=r"(a) : "l"(p));
    return a;
}
__device__ __forceinline__ void cp16(uint32_t dst, const void* src) {
    asm volatile("cp.async.cg.shared.global [%0], [%1], 16;"
                 :: "r"(dst), "l"(__cvta_generic_to_global(src)));
}
__device__ __forceinline__ void cp_commit() { asm volatile("cp.async.commit_group;"); }
__device__ __forceinline__ void cp_wait0()  { asm volatile("cp.async.wait_group 0;"); }

__device__ __forceinline__ float score_chain(float zz, float m, float ee) {
    return __fadd_rn(__fadd_rn(zz, -__fmul_rn(2.0f, m)), ee);
}

// ---------------- prep: fused transpose + bf16 A + z norms + init -----------
// One block per 32-pixel tile: stage [256 ch][32 px] in smem, write g_zt/g_abf
// coalesced, then 32 threads run the bit-exact sequential norm chain.
__global__ __launch_bounds__(256)
void transpose_znorm_kernel(const float* __restrict__ z) {
    __shared__ float s[CD][33];
    const int tid = threadIdx.x;
    const int p0 = blockIdx.x * 32;
    const int n = p0 >> 10;
    const int hw0 = p0 & 1023;

    // load: warp per channel row, 8 channels per iteration
#pragma unroll
    for (int i = 0; i < 32; ++i) {
        int c = i * 8 + (tid >> 5);
        s[c][tid & 31] = __ldg(&z[((size_t)(n * CD + c)) * HWSZ + hw0 + (tid & 31)]);
    }
    __syncthreads();

    // write transposed fp32 + bf16: thread t -> pixel px = t>>3, chunk t&7 (32 ch)
    {
        int px = tid >> 3, chunk = tid & 7;
        size_t base = ((size_t)(p0 + px)) * CD + chunk * 32;
#pragma unroll
        for (int k = 0; k < 32; k += 4) {
            int c = chunk * 32 + k;
            float4 v = make_float4(s[c][px], s[c + 1][px], s[c + 2][px], s[c + 3][px]);
            *(float4*)&g_zt[base + k] = v;
            __nv_bfloat162* d = (__nv_bfloat162*)&g_abf[base + k];
            d[0] = __floats2bfloat162_rn(v.x, v.y);
            d[1] = __floats2bfloat162_rn(v.z, v.w);
        }
    }

    // norms (XLA rounding: sequential ascending, mul rounded separately)
    if (tid < 32) {
        float acc = 0.f;
#pragma unroll 8
        for (int c = 0; c < CD; ++c) {
            float v = s[c][tid];
            acc = __fadd_rn(acc, __fmul_rn(v, v));
        }
        g_zn2[p0 + tid]    = acc;
        g_ccount[p0 + tid] = 0;
        g_best[p0 + tid]   = 0xFFFFFFFFFFFFFFFFull;
    }
}

// ---------------- prep: emb norms + bf16 B convert + npairs init ------------
__global__ __launch_bounds__(64)
void norms_kernel(const float* __restrict__ emb) {
    __shared__ float buf[CD];
    const int j = blockIdx.x;
    const int tid = threadIdx.x;

    if (j == 0 && tid == 0) g_npairs = 0u;

    const float4* src = (const float4*)(emb + (size_t)j * CD);
    float4 v = __ldg(&src[tid]);
    ((float4*)buf)[tid] = v;
    __nv_bfloat162* dst = (__nv_bfloat162*)(g_bbf + (size_t)j * CD);
    dst[tid * 2]     = __floats2bfloat162_rn(v.x, v.y);
    dst[tid * 2 + 1] = __floats2bfloat162_rn(v.z, v.w);
    __syncthreads();
    if (tid == 0) {
        float acc = 0.f;
#pragma unroll 16
        for (int k = 0; k < CD; ++k) {
            float w = buf[k];
            acc = __fadd_rn(acc, __fmul_rn(w, w));
        }
        g_en2[j] = acc;
    }
}

// ---------------- GEMM (mma.sync bf16) + candidate collection ----------------
// CTA: M=128 queries x N-group=1024 codes (8 blocks of 128), K=256.
#define SMA_STRIDE 264
#define SMB_STRIDE 72
#define SM_A       0
#define SM_B0      (128 * SMA_STRIDE * 2)
#define SM_BSZ     (128 * SMB_STRIDE * 2)
#define SM_B1      (SM_B0 + SM_BSZ)
#define SM_RMIN    (SM_B1 + SM_BSZ)
#define SMEM_TOTAL (SM_RMIN + 512)

__global__ __launch_bounds__(256, 2)
void gemm_cand_kernel() {
    extern __shared__ char smem[];
    const uint32_t sb = smem_u32(smem);
    const int tid = threadIdx.x, lane = tid & 31, warp = tid >> 5;
    const int warpM = warp >> 2;
    const int warpN = warp & 3;
    const int m0 = blockIdx.y * 128;
    const int g0 = blockIdx.x * 1024;
    unsigned* rowminU = (unsigned*)(smem + SM_RMIN);

    {
        const __nv_bfloat16* Ab = g_abf + (size_t)m0 * CD;
#pragma unroll
        for (int i = 0; i < 16; ++i) {
            int g = i * 256 + tid, row = g >> 5, grp = g & 31;
            cp16(sb + SM_A + row * (SMA_STRIDE * 2) + grp * 16, Ab + (size_t)row * CD + grp * 8);
        }
        cp_commit();
    }
    if (tid < 128) rowminU[tid] = 0x7F7FFFFFu;

    float zz0[4], zz1[4];
#pragma unroll
    for (int ti = 0; ti < 4; ++ti) {
        int r = m0 + warpM * 64 + ti * 16 + (lane >> 2);
        zz0[ti] = __ldg(&g_zn2[r]);
        zz1[ti] = __ldg(&g_zn2[r + 8]);
    }

    auto loadB = [&](int nbase, int kc, int buf) {
        const __nv_bfloat16* Bb = g_bbf + (size_t)nbase * CD + kc * 64;
        uint32_t dst = sb + (buf ? SM_B1 : SM_B0);
#pragma unroll
        for (int i = 0; i < 4; ++i) {
            int g = i * 256 + tid, row = g >> 3, grp = g & 7;
            cp16(dst + row * (SMB_STRIDE * 2) + grp * 16, Bb + (size_t)row * CD + grp * 8);
        }
        cp_commit();
    };

    const uint32_t aAddrBase = sb + SM_A + (warpM * 64 + (lane & 15)) * (SMA_STRIDE * 2) + (lane >> 4) * 16;
    const uint32_t bRowOff4  = (warpN * 32 + ((lane >> 4) << 3) + (lane & 7)) * (SMB_STRIDE * 2)
                             + ((lane >> 3) & 1) * 16;

    loadB(g0, 0, 0);

    for (int nb = 0; nb < 8; ++nb) {
        const int n0 = g0 + nb * 128;
        float c[4][4][4];
#pragma unroll
        for (int ti = 0; ti < 4; ++ti)
#pragma unroll
            for (int tj = 0; tj < 4; ++tj)
#pragma unroll
                for (int d = 0; d < 4; ++d) c[ti][tj][d] = 0.f;

#pragma unroll 1
        for (int kc = 0; kc < 4; ++kc) {
            const int buf = kc & 1;
            cp_wait0();
            __syncthreads();
            if (kc < 3)      loadB(n0, kc + 1, buf ^ 1);
            else if (nb < 7) loadB(n0 + 128, 0, 0);
            const uint32_t bBase = sb + (buf ? SM_B1 : SM_B0) + bRowOff4;
#pragma unroll
            for (int ks = 0; ks < 4; ++ks) {
                uint32_t a[4][4], b[2][4];
#pragma unroll
                for (int ti = 0; ti < 4; ++ti) {
                    uint32_t ad = aAddrBase + ti * 16 * (SMA_STRIDE * 2) + (kc * 64 + ks * 16) * 2;
                    asm volatile("ldmatrix.sync.aligned.m8n8.x4.shared.b16 {%0,%1,%2,%3}, [%4];"
                                 : "=r"(a[ti][0]), "=r"(a[ti][1]), "=r"(a[ti][2]), "=r"(a[ti][3])
                                 : "r"(ad));
                }
#pragma unroll
                for (int tjp = 0; tjp < 2; ++tjp) {
                    uint32_t bd = bBase + tjp * 16 * (SMB_STRIDE * 2) + (ks * 16) * 2;
                    asm volatile("ldmatrix.sync.aligned.m8n8.x4.shared.b16 {%0,%1,%2,%3}, [%4];"
                                 : "=r"(b[tjp][0]), "=r"(b[tjp][1]), "=r"(b[tjp][2]), "=r"(b[tjp][3])
                                 : "r"(bd));
                }
#pragma unroll
                for (int ti = 0; ti < 4; ++ti)
#pragma unroll
                    for (int tj = 0; tj < 4; ++tj) {
                        const uint32_t* bb = &b[tj >> 1][(tj & 1) * 2];
                        asm volatile(
                            "mma.sync.aligned.m16n8k16.row.col.f32.bf16.bf16.f32 "
                            "{%0,%1,%2,%3}, {%4,%5,%6,%7}, {%8,%9}, {%0,%1,%2,%3};"
                            : "+f"(c[ti][tj][0]), "+f"(c[ti][tj][1]),
                              "+f"(c[ti][tj][2]), "+f"(c[ti][tj][3])
                            : "r"(a[ti][0]), "r"(a[ti][1]), "r"(a[ti][2]), "r"(a[ti][3]),
                              "r"(bb[0]), "r"(bb[1]));
                    }
            }
        }

        float ee0[4], ee1[4];
#pragma unroll
        for (int tj = 0; tj < 4; ++tj) {
            int cidx = n0 + warpN * 32 + tj * 8 + 2 * (lane & 3);
            ee0[tj] = __ldg(&g_en2[cidx]);
            ee1[tj] = __ldg(&g_en2[cidx + 1]);
        }
#pragma unroll
        for (int ti = 0; ti < 4; ++ti) {
            float mn0 = 3.4e38f, mn1 = 3.4e38f;
#pragma unroll
            for (int tj = 0; tj < 4; ++tj) {
                float s0 = score_chain(zz0[ti], c[ti][tj][0], ee0[tj]);
                float s1 = score_chain(zz0[ti], c[ti][tj][1], ee1[tj]);
                float s2 = score_chain(zz1[ti], c[ti][tj][2], ee0[tj]);
                float s3 = score_chain(zz1[ti], c[ti][tj][3], ee1[tj]);
                c[ti][tj][0] = s0; c[ti][tj][1] = s1; c[ti][tj][2] = s2; c[ti][tj][3] = s3;
                mn0 = fminf(mn0, fminf(s0, s1));
                mn1 = fminf(mn1, fminf(s2, s3));
            }
            int r0 = warpM * 64 + ti * 16 + (lane >> 2);
            atomicMin(&rowminU[r0],     __float_as_uint(mn0));
            atomicMin(&rowminU[r0 + 8], __float_as_uint(mn1));
        }
        __syncthreads();
        // NOTE: no trailing sync after emission — threshold uses a running
        // (monotone-decreasing) rowmin, so any read ordering preserves the
        // candidate-superset guarantee; next nb's kc-loop sync restores full
        // ordering before smem-B reuse.
#pragma unroll
        for (int ti = 0; ti < 4; ++ti) {
            int r0 = warpM * 64 + ti * 16 + (lane >> 2);
            float t0 = __uint_as_float(rowminU[r0])     + CAND_MARGIN;
            float t1 = __uint_as_float(rowminU[r0 + 8]) + CAND_MARGIN;
            int q0 = m0 + r0, q1 = q0 + 8;
#pragma unroll
            for (int tj = 0; tj < 4; ++tj) {
                int cb = n0 + warpN * 32 + tj * 8 + 2 * (lane & 3);
                if (c[ti][tj][0] <= t0) {
                    int pos = atomicAdd(&g_ccount[q0], 1);
                    if (pos < MAXC) { g_cs[(size_t)q0 * MAXC + pos] = c[ti][tj][0]; g_ci[(size_t)q0 * MAXC + pos] = cb; }
                }
                if (c[ti][tj][1] <= t0) {
                    int pos = atomicAdd(&g_ccount[q0], 1);
                    if (pos < MAXC) { g_cs[(size_t)q0 * MAXC + pos] = c[ti][tj][1]; g_ci[(size_t)q0 * MAXC + pos] = cb + 1; }
                }
                if (c[ti][tj][2] <= t1) {
                    int pos = atomicAdd(&g_ccount[q1], 1);
                    if (pos < MAXC) { g_cs[(size_t)q1 * MAXC + pos] = c[ti][tj][2]; g_ci[(size_t)q1 * MAXC + pos] = cb; }
                }
                if (c[ti][tj][3] <= t1) {
                    int pos = atomicAdd(&g_ccount[q1], 1);
                    if (pos < MAXC) { g_cs[(size_t)q1 * MAXC + pos] = c[ti][tj][3]; g_ci[(size_t)q1 * MAXC + pos] = cb + 1; }
                }
            }
        }
    }
}

// ---------------- rescue phase A: survivor compaction, block-aggregated -----
__global__ __launch_bounds__(256)
void rescueA_kernel() {
    __shared__ int      blkCount;
    __shared__ unsigned gbase;
    __shared__ int      bq[512], bc[512];
    const int tid = threadIdx.x, lane = tid & 31, w = tid >> 5;
    const int q = blockIdx.x * 8 + w;
    if (tid == 0) blkCount = 0;
    __syncthreads();

    const int cnt = g_ccount[q];
    if (cnt <= 32) {
        float s = 3.4e38f; int ci = 0;
        if (lane < cnt) {
            s  = g_cs[(size_t)q * MAXC + lane];
            ci = g_ci[(size_t)q * MAXC + lane];
        }
        float mn = s;
#pragma unroll
        for (int o = 16; o; o >>= 1) mn = fminf(mn, __shfl_xor_sync(0xFFFFFFFFu, mn, o));
        bool pred = (lane < cnt) && (s <= mn + RESC_MARGIN);
        unsigned mask = __ballot_sync(0xFFFFFFFFu, pred);
        if (mask) {
            int leader = __ffs(mask) - 1;
            int base = 0;
            if (lane == leader) base = atomicAdd(&blkCount, __popc(mask));
            base = __shfl_sync(0xFFFFFFFFu, base, leader);
            if (pred) {
                int off = base + __popc(mask & ((1u << lane) - 1u));
                bq[off] = q; bc[off] = ci;
            }
        }
    } else if (cnt <= MAXC) {
        unsigned long long abest = 0xFFFFFFFFFFFFFFFFull;
        for (int base = 0; base < cnt; base += 32) {
            int i = base + lane;
            if (i < cnt) {
                float s = g_cs[(size_t)q * MAXC + i];
                unsigned long long k =
                    ((unsigned long long)__float_as_uint(s) << 32) | (unsigned)g_ci[(size_t)q * MAXC + i];
                abest = min(abest, k);
            }
        }
#pragma unroll
        for (int o = 16; o; o >>= 1) abest = min(abest, __shfl_xor_sync(0xFFFFFFFFu, abest, o));
        const float thr = __uint_as_float((uint32_t)(abest >> 32)) + RESC_MARGIN;
        for (int base = 0; base < cnt; base += 32) {
            int i = base + lane;
            bool pred = (i < cnt) && (g_cs[(size_t)q * MAXC + i] <= thr);
            unsigned mask = __ballot_sync(0xFFFFFFFFu, pred);
            if (!mask) continue;
            int leader = __ffs(mask) - 1;
            unsigned pbase = 0;
            if (lane == leader) pbase = atomicAdd(&g_npairs, (unsigned)__popc(mask));
            pbase = __shfl_sync(0xFFFFFFFFu, pbase, leader);
            if (pred) {
                unsigned off = pbase + __popc(mask & ((1u << lane) - 1u));
                if (off < PAIR_CAP) {
                    g_pq[off] = q;
                    g_pc[off] = g_ci[(size_t)q * MAXC + i];
                }
            }
        }
    } else {
        unsigned base;
        if (lane == 0) base = atomicAdd(&g_npairs, (unsigned)N_CODE);
        base = __shfl_sync(0xFFFFFFFFu, base, 0);
        if (base + N_CODE <= PAIR_CAP) {
            for (int j = lane; j < N_CODE; j += 32) {
                g_pq[base + j] = q; g_pc[base + j] = j;
            }
        }
    }

    __syncthreads();
    if (tid == 0 && blkCount > 0) gbase = atomicAdd(&g_npairs, (unsigned)blkCount);
    __syncthreads();
    for (int i = tid; i < blkCount; i += 256) {
        unsigned off = gbase + i;
        if (off < PAIR_CAP) { g_pq[off] = bq[i]; g_pc[off] = bc[i]; }
    }
}

// ---------------- rescue phase B: dense exact eval (thread per pair) --------
__global__ __launch_bounds__(256)
void rescueB_kernel(const float* __restrict__ emb) {
    unsigned n = g_npairs;
    if (n > PAIR_CAP) n = PAIR_CAP;
    const unsigned stride = gridDim.x * blockDim.x;
    for (unsigned i = blockIdx.x * blockDim.x + threadIdx.x; i < n; i += stride) {
        const int q = g_pq[i];
        const int code = g_pc[i];
        const float4* zr = (const float4*)(g_zt + (size_t)q * CD);
        const float4* er = (const float4*)(emb + (size_t)code * CD);
        float acc = 0.f;
#pragma unroll 8
        for (int k4 = 0; k4 < CD / 4; ++k4) {
            float4 a = __ldg(&zr[k4]);
            float4 b = __ldg(&er[k4]);
            acc = fmaf(a.x, b.x, acc);
            acc = fmaf(a.y, b.y, acc);
            acc = fmaf(a.z, b.z, acc);
            acc = fmaf(a.w, b.w, acc);
        }
        float d = __fadd_rn(__fadd_rn(__ldg(&g_zn2[q]), -__fmul_rn(2.0f, acc)), __ldg(&g_en2[code]));
        unsigned long long key = ((unsigned long long)__float_as_uint(d) << 32) | (unsigned)code;
        atomicMin(&g_best[q], key);
    }
}

// ---------------- gather: smem-transposed (coalesced emb reads) -------------
__global__ __launch_bounds__(256)
void gather_kernel(const float* __restrict__ z, const float* __restrict__ emb,
                   float* __restrict__ out) {
    __shared__ float sq[32][257];
    __shared__ int   sidx[32];
    const int tid = threadIdx.x, lane = tid & 31, w = tid >> 5;
    const int p0 = blockIdx.x * 32;

    if (tid < 32) sidx[tid] = (int)(g_best[p0 + tid] & 0x1FFFull);
    __syncthreads();

#pragma unroll
    for (int k = 0; k < 4; ++k) {
        int pp = w * 4 + k;
        const float4* er = (const float4*)(emb + (size_t)sidx[pp] * CD);
        float4 a = __ldg(&er[lane]);
        float4 b = __ldg(&er[lane + 32]);
        sq[pp][lane * 4 + 0]   = a.x; sq[pp][lane * 4 + 1]   = a.y;
        sq[pp][lane * 4 + 2]   = a.z; sq[pp][lane * 4 + 3]   = a.w;
        sq[pp][128 + lane * 4 + 0] = b.x; sq[pp][128 + lane * 4 + 1] = b.y;
        sq[pp][128 + lane * 4 + 2] = b.z; sq[pp][128 + lane * 4 + 3] = b.w;
    }
    __syncthreads();

    const int p  = p0 + lane;
    const int n  = p >> 10;
    const int hw = p & 1023;
    const size_t base = (size_t)n * (CD * HWSZ) + hw;
#pragma unroll
    for (int cc = 0; cc < CD / 8; ++cc) {
        int c = cc * 8 + w;
        float qv = sq[lane][c];
        size_t off = base + (size_t)c * HWSZ;
        out[off] = qv;
        float zv = z[off];
        out[OFF_ST + off] = __fadd_rn(zv, __fadd_rn(qv, -zv));
    }
    if (w == 0) out[OFF_IDX + p] = (float)sidx[lane];
}

// ---------------------------------------------------------------------------
extern "C" void kernel_launch(void* const* d_in, const int* in_sizes, int n_in,
                              void* d_out, int out_size) {
    const float* z   = (const float*)d_in[0];
    const float* emb = (const float*)d_in[1];
    float* out = (float*)d_out;

    cudaFuncSetAttribute(gemm_cand_kernel, cudaFuncAttributeMaxDynamicSharedMemorySize, SMEM_TOTAL);

    transpose_znorm_kernel<<<N_PIX / 32, 256>>>(z);
    norms_kernel<<<N_CODE, 64>>>(emb);
    gemm_cand_kernel<<<dim3(N_CODE / 1024, N_PIX / 128), 256, SMEM_TOTAL>>>();
    rescueA_kernel<<<N_PIX / 8, 256>>>();
    rescueB_kernel<<<256, 256>>>(emb);
    gather_kernel<<<N_PIX / 32, 256>>>(z, emb, out);
}